// round 15
// baseline (speedup 1.0000x reference)
#include <cuda_runtime.h>
#include <cuda_fp16.h>
#include <cstdint>

// ============================================================================
// out[m,n] = sum_e softmax(x@Wg+bg)[m,e] * (x@We[e] + be[e])[n]
// R14 = R13 with the A-fragment gate pairing FIXED:
//   mma.m16n8k16 A regs: {a0,a2} -> row lane/4 ; {a1,a3} -> row lane/4+8.
// GEMM streams xh (fp16 x, 16MB, L2-resident) as A and applies gate g[m,e]
// to A fragments in registers per 16-iter expert segment.
// W'[n][e*1024+k] = We[e,k,n] (fp16, 16MB).  Split-K=4, deterministic
// reduce adds partials + gate-weighted bias.
// ============================================================================

#define NE 8
#define INF 1024
#define OUTF 1024
#define NTOK 8192
#define KSEG 8192            // NE*INF
#define NSPLIT 4
#define ITERS_PER_SPLIT 32   // 2 experts * 16 iters(BK=64)

// GEMM tile config (R10/R12-proven inner loop)
#define BM 128
#define BN 128
#define BK 64
#define THREADS 256
#define STAGES 3
#define STAGE_BYTES 32768    // (BM+BN)*BK*2
#define SB_B_OFF 16384       // A: 16KB then B: 16KB
#define SMEM_BYTES (STAGES * STAGE_BYTES)   // 96KB -> 2 CTAs/SM
#define VSTRIDE_A (32 * INF * 2)            // 64KB   (32 rows of xh)
#define VSTRIDE_B (32 * KSEG * 2)           // 512KB  (32 rows of W')

// ---- scratch (device globals; no allocation allowed) ----
__device__ __align__(16) float  g_G[NTOK * NE];                       // gate
__device__ __align__(16) __half g_X[(size_t)NTOK * INF];              // 16MB
__device__ __align__(16) __half g_W[(size_t)OUTF * KSEG];             // 16MB
__device__ __align__(16) float  g_P[3 * (size_t)NTOK * OUTF];         // 96MB

// ============================================================================
// PTX helpers — baseline (sm_80-class) only
// ============================================================================
__device__ __forceinline__ uint32_t smem_u32(const void* p) {
    uint32_t a;
    asm("{ .reg .u64 t; cvta.to.shared.u64 t, %1; cvt.u32.u64 %0, t; }"
        : "=r"(a) : "l"(p));
    return a;
}

#define CP_ASYNC16(saddr, gaddr) \
    asm volatile("cp.async.cg.shared.global [%0], [%1], 16;" \
                 :: "r"(saddr), "l"(gaddr))

#define CP_COMMIT() asm volatile("cp.async.commit_group;" ::: "memory")
#define CP_WAIT1()  asm volatile("cp.async.wait_group 1;" ::: "memory")
#define CP_WAIT0()  asm volatile("cp.async.wait_group 0;" ::: "memory")

#define LDSM_X4(r0, r1, r2, r3, addr) \
    asm volatile("ldmatrix.sync.aligned.m8n8.x4.shared.b16 {%0,%1,%2,%3}, [%4];" \
                 : "=r"(r0), "=r"(r1), "=r"(r2), "=r"(r3) : "r"(addr))

#define MMA_16816(c, a, b0v, b1v) \
    asm volatile("mma.sync.aligned.m16n8k16.row.col.f32.f16.f16.f32 " \
                 "{%0,%1,%2,%3}, {%4,%5,%6,%7}, {%8,%9}, {%0,%1,%2,%3};" \
                 : "+f"((c)[0]), "+f"((c)[1]), "+f"((c)[2]), "+f"((c)[3]) \
                 : "r"((a)[0]), "r"((a)[1]), "r"((a)[2]), "r"((a)[3]), \
                   "r"(b0v), "r"(b1v))

#define MULH2(d, a, b) \
    asm("mul.rn.f16x2 %0, %1, %2;" : "=r"(d) : "r"(a), "r"(b))

__device__ __forceinline__ uint32_t splat_h2(float f) {
    __half h = __float2half_rn(f);
    __half2 hh = __half2half2(h);
    return *(uint32_t*)&hh;
}

// ============================================================================
// Prep 1: gate softmax -> g_G ; convert x -> fp16 g_X.  Block = 8 tokens.
// ============================================================================
__global__ __launch_bounds__(256) void gate_xh_kernel(
    const float* __restrict__ x, const float* __restrict__ Wg,
    const float* __restrict__ bg) {
    __shared__ float wgs[INF * NE];   // 32KB
    int tid = threadIdx.x;
    for (int i = tid; i < INF * NE / 4; i += 256)
        ((float4*)wgs)[i] = ((const float4*)Wg)[i];
    __syncthreads();

    int w = tid >> 5, lane = tid & 31;
    int t = blockIdx.x * 8 + w;
    const float* xr = x + (size_t)t * INF;

    float acc[NE];
#pragma unroll
    for (int e = 0; e < NE; e++) acc[e] = 0.f;
    for (int i = lane; i < INF; i += 32) {
        float xv = xr[i];
        float4 a = ((const float4*)wgs)[i * 2];
        float4 b = ((const float4*)wgs)[i * 2 + 1];
        acc[0] += xv * a.x; acc[1] += xv * a.y; acc[2] += xv * a.z; acc[3] += xv * a.w;
        acc[4] += xv * b.x; acc[5] += xv * b.y; acc[6] += xv * b.z; acc[7] += xv * b.w;
    }
#pragma unroll
    for (int e = 0; e < NE; e++)
#pragma unroll
        for (int off = 16; off; off >>= 1)
            acc[e] += __shfl_xor_sync(0xffffffffu, acc[e], off);

    if (lane == 0) {
        float mx = -1e30f;
#pragma unroll
        for (int e = 0; e < NE; e++) { acc[e] += bg[e]; mx = fmaxf(mx, acc[e]); }
        float s = 0.f;
#pragma unroll
        for (int e = 0; e < NE; e++) { acc[e] = expf(acc[e] - mx); s += acc[e]; }
        float inv = 1.0f / s;
#pragma unroll
        for (int e = 0; e < NE; e++) g_G[t * NE + e] = acc[e] * inv;
    }

    // convert this block's 8 x-rows to fp16 (1024 chunks of 8 halves)
    for (int u = tid; u < 1024; u += 256) {
        int row = u >> 7;
        int k8  = (u & 127) << 3;
        int m = blockIdx.x * 8 + row;
        const float* xs = x + (size_t)m * INF + k8;
        float4 a = ((const float4*)xs)[0];
        float4 b = ((const float4*)xs)[1];
        float v[8] = {a.x, a.y, a.z, a.w, b.x, b.y, b.z, b.w};
        __align__(16) __half h[8];
#pragma unroll
        for (int i = 0; i < 8; i++) h[i] = __float2half_rn(v[i]);
        *(uint4*)(g_X + (size_t)m * INF + k8) = *(const uint4*)h;
    }
}

// ============================================================================
// Prep 2: W'[n][e*1024+k] = fp16(We[e][k][n])  (smem transpose)
// ============================================================================
__global__ __launch_bounds__(256) void splitw_kernel(const float* __restrict__ We) {
    int b  = blockIdx.x;            // 8 * 32 * 32 = 8192 blocks
    int e  = b >> 10;
    int kt = (b >> 5) & 31;
    int nt = b & 31;

    __shared__ float tile[32][33];
    int tx = threadIdx.x & 31, ty = threadIdx.x >> 5;
    const float* base = We + (size_t)e * INF * OUTF;

#pragma unroll
    for (int i = 0; i < 4; i++) {
        int k = kt * 32 + ty + i * 8;
        tile[ty + i * 8][tx] = base[(size_t)k * OUTF + nt * 32 + tx];
    }
    __syncthreads();
#pragma unroll
    for (int i = 0; i < 4; i++) {
        int nrow = nt * 32 + ty + i * 8;
        float v = tile[tx][ty + i * 8];
        g_W[(size_t)nrow * KSEG + e * INF + kt * 32 + tx] = __float2half_rn(v);
    }
}

// ============================================================================
// Main GEMM (split-K=4, gate applied to A fragments in registers).
// CTA 128x128x64, 256 thr (8 warps 2m x 4n, warp tile 64x32), 3-stage
// cp.async, 2 CTAs per SM.  Split sp covers experts {2sp, 2sp+1} = 32 iters.
// ============================================================================
__device__ __forceinline__ void issue_stage(uint32_t stb, const char* gA,
                                            const char* gB, uint32_t sAo,
                                            int j) {
    int aoff = (j & 15) * 128;     // x column cycles every expert
    int boff = j * 128;            // W column advances monotonically
#pragma unroll
    for (int v = 0; v < 4; v++)
        CP_ASYNC16(stb + sAo + v * 4096, gA + aoff + (size_t)v * VSTRIDE_A);
#pragma unroll
    for (int v = 0; v < 4; v++)
        CP_ASYNC16(stb + SB_B_OFF + sAo + v * 4096,
                   gB + boff + (size_t)v * VSTRIDE_B);
    CP_COMMIT();
}

__global__ __launch_bounds__(THREADS, 2) void moe_gemm_kernel(
    float* __restrict__ out, float* __restrict__ part) {
    extern __shared__ __align__(128) char smem[];
    uint32_t sb = smem_u32(smem);

    int tid  = threadIdx.x;
    int lane = tid & 31;
    int wid  = tid >> 5;
    int wm   = wid & 1;          // 2 warp-rows  (m)  64 rows each
    int wn   = wid >> 1;         // 4 warp-cols  (n)  32 cols each
    int m0   = blockIdx.y * BM;
    int n0   = blockIdx.x * BN;
    int sp   = blockIdx.z;       // split id 0..3

    // ---- cp.async per-thread invariants ----
    int rA = tid >> 3;           // 0..31
    int ch = tid & 7;
    const char* gA = (const char*)(g_X + (size_t)(m0 + rA) * INF + ch * 8);
    const char* gB = (const char*)(g_W + (size_t)(n0 + rA) * KSEG + ch * 8)
                     + (size_t)sp * ITERS_PER_SPLIT * 128;
    uint32_t sAo = (uint32_t)(rA * 128 + ((ch ^ (rA & 7)) << 4));

    // ---- ldmatrix per-thread invariants ----
    int aRow0 = wm * 64 + (lane & 15);
    int ah    = lane >> 4;
    int ax7   = aRow0 & 7;
    int bRow0 = wn * 32 + (lane & 7) + ((lane >> 4) << 3);
    int bh    = (lane >> 3) & 1;
    int bx7   = bRow0 & 7;
    int mBase = m0 + wm * 64 + (lane >> 2);   // fragment row (and +8)

    uint32_t aBase[4], bBase[2];
#pragma unroll
    for (int mt = 0; mt < 4; mt++) aBase[mt] = (uint32_t)((aRow0 + mt * 16) * 128);
#pragma unroll
    for (int np = 0; np < 2; np++)
        bBase[np] = (uint32_t)(SB_B_OFF + (bRow0 + np * 16) * 128);

    float acc[4][4][4];
#pragma unroll
    for (int mt = 0; mt < 4; mt++)
#pragma unroll
        for (int nt = 0; nt < 4; nt++)
#pragma unroll
            for (int q = 0; q < 4; q++) acc[mt][nt][q] = 0.f;

    uint32_t gmA[4], gmB[4];     // gate splats for fragment rows r, r+8

    // ---- prologue: stages 0,1 ----
    issue_stage(sb + 0 * STAGE_BYTES, gA, gB, sAo, 0);
    issue_stage(sb + 1 * STAGE_BYTES, gA, gB, sAo, 1);

    // ---- main loop: 32 iters = 2 experts x 16 ----
    int buf = 0;
    for (int j = 0; j < ITERS_PER_SPLIT; j++) {
        if ((j & 15) == 0) {
            int e = 2 * sp + (j >> 4);
#pragma unroll
            for (int mt = 0; mt < 4; mt++) {
                gmA[mt] = splat_h2(g_G[(size_t)(mBase + mt * 16) * NE + e]);
                gmB[mt] = splat_h2(g_G[(size_t)(mBase + mt * 16 + 8) * NE + e]);
            }
        }

        if (j < ITERS_PER_SPLIT - 1) CP_WAIT1(); else CP_WAIT0();
        __syncthreads();

        if (j + 2 < ITERS_PER_SPLIT) {
            int nb = buf + 2; if (nb >= STAGES) nb -= STAGES;
            issue_stage(sb + nb * STAGE_BYTES, gA, gB, sAo, j + 2);
        }

        uint32_t stb = sb + buf * STAGE_BYTES;
        if (++buf == STAGES) buf = 0;

#pragma unroll
        for (int s = 0; s < 4; s++) {
            uint32_t cpA = (uint32_t)(((2 * s + ah) ^ ax7) << 4);
            uint32_t cpB = (uint32_t)(((2 * s + bh) ^ bx7) << 4);

            uint32_t af[4][4], bf[2][4];
#pragma unroll
            for (int mt = 0; mt < 4; mt++)
                LDSM_X4(af[mt][0], af[mt][1], af[mt][2], af[mt][3],
                        stb + aBase[mt] + cpA);
#pragma unroll
            for (int np = 0; np < 2; np++)
                LDSM_X4(bf[np][0], bf[np][1], bf[np][2], bf[np][3],
                        stb + bBase[np] + cpB);

            // gate scaling — mma.m16n8k16 A-fragment row mapping:
            //   {a0, a2} -> row lane/4   (gmA)
            //   {a1, a3} -> row lane/4+8 (gmB)
#pragma unroll
            for (int mt = 0; mt < 4; mt++) {
                MULH2(af[mt][0], af[mt][0], gmA[mt]);
                MULH2(af[mt][2], af[mt][2], gmA[mt]);
                MULH2(af[mt][1], af[mt][1], gmB[mt]);
                MULH2(af[mt][3], af[mt][3], gmB[mt]);
            }

#pragma unroll
            for (int mt = 0; mt < 4; mt++)
#pragma unroll
                for (int np = 0; np < 2; np++) {
                    MMA_16816(acc[mt][2 * np + 0], af[mt], bf[np][0], bf[np][1]);
                    MMA_16816(acc[mt][2 * np + 1], af[mt], bf[np][2], bf[np][3]);
                }
        }
    }

    // ---- epilogue: split 0 -> out, splits 1..3 -> g_P slabs ----
    float* dst = (sp == 0) ? out : (part + (size_t)(sp - 1) * NTOK * OUTF);
    int grp = lane >> 2;
    int tig = lane & 3;
#pragma unroll
    for (int mt = 0; mt < 4; mt++) {
        int mrow = m0 + wm * 64 + mt * 16 + grp;
#pragma unroll
        for (int nt = 0; nt < 4; nt++) {
            int ncol = n0 + wn * 32 + nt * 8 + tig * 2;
            float2 v0 = make_float2(acc[mt][nt][0], acc[mt][nt][1]);
            float2 v1 = make_float2(acc[mt][nt][2], acc[mt][nt][3]);
            *(float2*)(dst + (size_t)mrow * OUTF + ncol)       = v0;
            *(float2*)(dst + (size_t)(mrow + 8) * OUTF + ncol) = v1;
        }
    }
}

// ============================================================================
// Reduce: out += P1 + P2 + P3 + sum_e g[m,e]*be[e,n]   (deterministic)
// ============================================================================
__global__ __launch_bounds__(256) void reduce_bias_kernel(
    float* __restrict__ out, const float* __restrict__ be) {
    size_t i4 = ((size_t)blockIdx.x * 256 + threadIdx.x) * 4;
    int m = (int)(i4 >> 10);
    int n = (int)(i4 & 1023);

    float4 a = *(float4*)(out + i4);
#pragma unroll
    for (int s = 0; s < 3; s++) {
        float4 p = *(const float4*)(g_P + (size_t)s * NTOK * OUTF + i4);
        a.x += p.x; a.y += p.y; a.z += p.z; a.w += p.w;
    }
    const float* g = g_G + (size_t)m * NE;
#pragma unroll
    for (int e = 0; e < NE; e++) {
        float ge = g[e];
        float4 bv = *(const float4*)(be + (size_t)e * OUTF + n);
        a.x += ge * bv.x; a.y += ge * bv.y;
        a.z += ge * bv.z; a.w += ge * bv.w;
    }
    *(float4*)(out + i4) = a;
}

// ============================================================================
// Launch
// ============================================================================
extern "C" void kernel_launch(void* const* d_in, const int* in_sizes, int n_in,
                              void* d_out, int out_size) {
    (void)in_sizes; (void)n_in; (void)out_size;
    const float* x  = (const float*)d_in[0];   // [8192, 1024]
    const float* We = (const float*)d_in[1];   // [8, 1024, 1024]
    const float* be = (const float*)d_in[2];   // [8, 1024]
    const float* Wg = (const float*)d_in[3];   // [1024, 8]
    const float* bg = (const float*)d_in[4];   // [8]
    float* out = (float*)d_out;                // [8192, 1024]

    float* part;
    cudaGetSymbolAddress((void**)&part, g_P);

    cudaFuncSetAttribute(moe_gemm_kernel,
                         cudaFuncAttributeMaxDynamicSharedMemorySize, SMEM_BYTES);

    gate_xh_kernel<<<NTOK / 8, 256>>>(x, Wg, bg);
    splitw_kernel<<<NE * 32 * 32, 256>>>(We);
    moe_gemm_kernel<<<dim3(OUTF / BN, NTOK / BM, NSPLIT), THREADS, SMEM_BYTES>>>(
        out, part);
    reduce_bias_kernel<<<(NTOK * OUTF) / (256 * 4), 256>>>(out, be);
}

// round 16
// speedup vs baseline: 1.0297x; 1.0297x over previous
#include <cuda_runtime.h>
#include <cuda_fp16.h>
#include <cstdint>

// ============================================================================
// out[m,n] = sum_e softmax(x@Wg+bg)[m,e] * (x@We[e] + be[e])[n]
// Fused single GEMM (fp16 in / fp32 accum via mma.sync):
//   A'[m, e*1024+k] = g[m,e]*x[m,k], bias tail A'[m,8192+e]=g[m,e]
//   W'[n][e*1024+k] = We[e,k,n],     bias tail W'[n][8192+e]=be[e,n]
//   K_ext = 8256 ;  out = A' @ W'^T   (M=8192, N=1024)
// R15: R12's proven inner loop (materialized A', zero in-loop gate cost)
// + split-K=4 (makespan 288 -> 256 iter-units). Splits {33,32,32,32};
// split 0 -> out, splits 1-3 -> g_P slabs; deterministic 3-way reduce.
// ============================================================================

#define NE 8
#define INF 1024
#define OUTF 1024
#define NTOK 8192
#define KSEG 8192
#define KTOT 8256            // 8192 + 64 (bias tail, zero padded)
#define KI 129               // KTOT / 64
#define NSPLIT 4

// GEMM tile config (R10/R12-proven)
#define BM 128
#define BN 128
#define BK 64
#define THREADS 256
#define STAGES 3
#define STAGE_BYTES 32768    // (BM+BN)*BK*2
#define SB_B_OFF 16384       // A: 16KB then B: 16KB
#define SMEM_BYTES (STAGES * STAGE_BYTES)   // 96KB -> 2 CTAs/SM
#define VSTRIDE32 (32 * KTOT * 2)           // 32 rows of fp16

// ---- scratch (device globals; no allocation allowed) ----
__device__ __align__(16) __half g_A[(size_t)NTOK * KTOT];   // ~135 MB
__device__ __align__(16) __half g_W[(size_t)OUTF * KTOT];   // ~17 MB
__device__ __align__(16) float  g_P[3 * (size_t)NTOK * OUTF];  // 96 MB partials

// ============================================================================
// PTX helpers — baseline (sm_80-class) only
// ============================================================================
__device__ __forceinline__ uint32_t smem_u32(const void* p) {
    uint32_t a;
    asm("{ .reg .u64 t; cvta.to.shared.u64 t, %1; cvt.u32.u64 %0, t; }"
        : "=r"(a) : "l"(p));
    return a;
}

#define CP_ASYNC16(saddr, gaddr) \
    asm volatile("cp.async.cg.shared.global [%0], [%1], 16;" \
                 :: "r"(saddr), "l"(gaddr))

#define CP_COMMIT() asm volatile("cp.async.commit_group;" ::: "memory")
#define CP_WAIT1()  asm volatile("cp.async.wait_group 1;" ::: "memory")
#define CP_WAIT0()  asm volatile("cp.async.wait_group 0;" ::: "memory")

#define LDSM_X4(r0, r1, r2, r3, addr) \
    asm volatile("ldmatrix.sync.aligned.m8n8.x4.shared.b16 {%0,%1,%2,%3}, [%4];" \
                 : "=r"(r0), "=r"(r1), "=r"(r2), "=r"(r3) : "r"(addr))

#define MMA_16816(c, a, b0v, b1v) \
    asm volatile("mma.sync.aligned.m16n8k16.row.col.f32.f16.f16.f32 " \
                 "{%0,%1,%2,%3}, {%4,%5,%6,%7}, {%8,%9}, {%0,%1,%2,%3};" \
                 : "+f"((c)[0]), "+f"((c)[1]), "+f"((c)[2]), "+f"((c)[3]) \
                 : "r"((a)[0]), "r"((a)[1]), "r"((a)[2]), "r"((a)[3]), \
                   "r"(b0v), "r"(b1v))

// ============================================================================
// Prep 1 (fused): gate softmax + A' write (+ bias tail of A)
// ============================================================================
__global__ __launch_bounds__(256) void gate_splitx_kernel(
    const float* __restrict__ x, const float* __restrict__ Wg,
    const float* __restrict__ bg) {
    __shared__ float wgs[INF * NE];   // 32KB
    __shared__ float gs[8][NE];
    int tid = threadIdx.x;
    for (int i = tid; i < INF * NE / 4; i += 256)
        ((float4*)wgs)[i] = ((const float4*)Wg)[i];
    __syncthreads();

    int w = tid >> 5, lane = tid & 31;
    int t = blockIdx.x * 8 + w;
    const float* xr = x + (size_t)t * INF;

    float acc[NE];
#pragma unroll
    for (int e = 0; e < NE; e++) acc[e] = 0.f;
    for (int i = lane; i < INF; i += 32) {
        float xv = xr[i];
        float4 a = ((const float4*)wgs)[i * 2];
        float4 b = ((const float4*)wgs)[i * 2 + 1];
        acc[0] += xv * a.x; acc[1] += xv * a.y; acc[2] += xv * a.z; acc[3] += xv * a.w;
        acc[4] += xv * b.x; acc[5] += xv * b.y; acc[6] += xv * b.z; acc[7] += xv * b.w;
    }
#pragma unroll
    for (int e = 0; e < NE; e++)
#pragma unroll
        for (int off = 16; off; off >>= 1)
            acc[e] += __shfl_xor_sync(0xffffffffu, acc[e], off);

    if (lane == 0) {
        float mx = -1e30f;
#pragma unroll
        for (int e = 0; e < NE; e++) { acc[e] += bg[e]; mx = fmaxf(mx, acc[e]); }
        float s = 0.f;
#pragma unroll
        for (int e = 0; e < NE; e++) { acc[e] = expf(acc[e] - mx); s += acc[e]; }
        float inv = 1.0f / s;
#pragma unroll
        for (int e = 0; e < NE; e++) gs[w][e] = acc[e] * inv;
    }
    __syncthreads();

#pragma unroll 1
    for (int tok = 0; tok < 8; tok++) {
        int m = blockIdx.x * 8 + tok;
        const float* xs = x + (size_t)m * INF;
        __half* arow = g_A + (size_t)m * KTOT;
        for (int u = tid; u < 1024; u += 256) {
            int e  = u >> 7;
            int k8 = (u & 127) << 3;
            float g = gs[tok][e];
            float4 a = ((const float4*)(xs + k8))[0];
            float4 b = ((const float4*)(xs + k8))[1];
            float v[8] = {a.x, a.y, a.z, a.w, b.x, b.y, b.z, b.w};
            __align__(16) __half h[8];
#pragma unroll
            for (int i = 0; i < 8; i++) h[i] = __float2half_rn(g * v[i]);
            *(uint4*)(arow + e * INF + k8) = *(const uint4*)h;
        }
        for (int j = tid; j < 64; j += 256)
            arow[KSEG + j] = (j < NE) ? __float2half_rn(gs[tok][j]) : __half(0.f);
    }
}

// ============================================================================
// Prep 2: W'[n][e*1024+k] = fp16(We[e][k][n])  (smem transpose)
// ============================================================================
__global__ __launch_bounds__(256) void splitw_kernel(const float* __restrict__ We) {
    int b  = blockIdx.x;            // 8 * 32 * 32 = 8192 blocks
    int e  = b >> 10;
    int kt = (b >> 5) & 31;
    int nt = b & 31;

    __shared__ float tile[32][33];
    int tx = threadIdx.x & 31, ty = threadIdx.x >> 5;
    const float* base = We + (size_t)e * INF * OUTF;

#pragma unroll
    for (int i = 0; i < 4; i++) {
        int k = kt * 32 + ty + i * 8;
        tile[ty + i * 8][tx] = base[(size_t)k * OUTF + nt * 32 + tx];
    }
    __syncthreads();
#pragma unroll
    for (int i = 0; i < 4; i++) {
        int nrow = nt * 32 + ty + i * 8;
        float v = tile[tx][ty + i * 8];
        g_W[(size_t)nrow * KTOT + e * INF + kt * 32 + tx] = __float2half_rn(v);
    }
}

// Tail of W: W'[n][8192+j] = (j<8) ? be[j][n] : 0
__global__ __launch_bounds__(256) void tail_w_kernel(const float* __restrict__ be) {
    int idx = blockIdx.x * 256 + threadIdx.x;
    int n = idx >> 6;
    int j = idx & 63;
    g_W[(size_t)n * KTOT + KSEG + j] =
        (j < NE) ? __float2half_rn(be[(size_t)j * OUTF + n]) : __half(0.f);
}

// ============================================================================
// Main GEMM (split-K=4): split 0 -> out, splits 1..3 -> g_P slabs.
// CTA 128x128x64, 256 thr (8 warps 2m x 4n, warp tile 64x32), 3-stage
// cp.async, 2 CTAs per SM.
// ============================================================================
__device__ __forceinline__ void issue_stage(uint32_t stb, const char* gA,
                                            const char* gB, uint32_t sAo,
                                            int kbyte) {
#pragma unroll
    for (int v = 0; v < 4; v++)
        CP_ASYNC16(stb + sAo + v * 4096, gA + kbyte + (size_t)v * VSTRIDE32);
#pragma unroll
    for (int v = 0; v < 4; v++)
        CP_ASYNC16(stb + SB_B_OFF + sAo + v * 4096,
                   gB + kbyte + (size_t)v * VSTRIDE32);
    CP_COMMIT();
}

__global__ __launch_bounds__(THREADS, 2) void moe_gemm_kernel(
    float* __restrict__ out, float* __restrict__ part) {
    extern __shared__ __align__(128) char smem[];
    uint32_t sb = smem_u32(smem);

    int tid  = threadIdx.x;
    int lane = tid & 31;
    int wid  = tid >> 5;
    int wm   = wid & 1;          // 2 warp-rows  (m)  64 rows each
    int wn   = wid >> 1;         // 4 warp-cols  (n)  32 cols each
    int m0   = blockIdx.y * BM;
    int n0   = blockIdx.x * BN;
    int sp   = blockIdx.z;       // split id 0..3
    int it0  = (sp == 0) ? 0 : (33 + 32 * (sp - 1));
    int nIt  = sp ? 32 : 33;     // 33+32+32+32 = 129

    // ---- cp.async per-thread invariants (256 thr: 32 rows x 8 chunks) ----
    int rA = tid >> 3;           // 0..31
    int ch = tid & 7;
    const char* gA = (const char*)(g_A + (size_t)(m0 + rA) * KTOT + ch * 8)
                     + (size_t)it0 * 128;
    const char* gB = (const char*)(g_W + (size_t)(n0 + rA) * KTOT + ch * 8)
                     + (size_t)it0 * 128;
    uint32_t sAo = (uint32_t)(rA * 128 + ((ch ^ (rA & 7)) << 4));

    // ---- ldmatrix per-thread invariants ----
    int aRow0 = wm * 64 + (lane & 15);
    int ah    = lane >> 4;
    int ax7   = aRow0 & 7;
    int bRow0 = wn * 32 + (lane & 7) + ((lane >> 4) << 3);
    int bh    = (lane >> 3) & 1;
    int bx7   = bRow0 & 7;

    uint32_t aBase[4], bBase[2];
#pragma unroll
    for (int mt = 0; mt < 4; mt++) aBase[mt] = (uint32_t)((aRow0 + mt * 16) * 128);
#pragma unroll
    for (int np = 0; np < 2; np++)
        bBase[np] = (uint32_t)(SB_B_OFF + (bRow0 + np * 16) * 128);

    float acc[4][4][4];
#pragma unroll
    for (int mt = 0; mt < 4; mt++)
#pragma unroll
        for (int nt = 0; nt < 4; nt++)
#pragma unroll
            for (int q = 0; q < 4; q++) acc[mt][nt][q] = 0.f;

    // ---- prologue: stages 0,1 (relative to it0) ----
    issue_stage(sb + 0 * STAGE_BYTES, gA, gB, sAo, 0 * 128);
    issue_stage(sb + 1 * STAGE_BYTES, gA, gB, sAo, 1 * 128);

    // ---- main loop ----
    int buf = 0;                      // relative stage i lives in buffer (i % 3)
    for (int i = 0; i < nIt; i++) {
        if (i < nIt - 1) CP_WAIT1(); else CP_WAIT0();
        __syncthreads();

        if (i + 2 < nIt) {
            int nb = buf + 2; if (nb >= STAGES) nb -= STAGES;
            issue_stage(sb + nb * STAGE_BYTES, gA, gB, sAo, (i + 2) * 128);
        }

        uint32_t stb = sb + buf * STAGE_BYTES;
        if (++buf == STAGES) buf = 0;

#pragma unroll
        for (int s = 0; s < 4; s++) {
            uint32_t cpA = (uint32_t)(((2 * s + ah) ^ ax7) << 4);
            uint32_t cpB = (uint32_t)(((2 * s + bh) ^ bx7) << 4);

            uint32_t af[4][4], bf[2][4];
#pragma unroll
            for (int mt = 0; mt < 4; mt++)
                LDSM_X4(af[mt][0], af[mt][1], af[mt][2], af[mt][3],
                        stb + aBase[mt] + cpA);
#pragma unroll
            for (int np = 0; np < 2; np++)
                LDSM_X4(bf[np][0], bf[np][1], bf[np][2], bf[np][3],
                        stb + bBase[np] + cpB);

#pragma unroll
            for (int mt = 0; mt < 4; mt++)
#pragma unroll
                for (int np = 0; np < 2; np++) {
                    MMA_16816(acc[mt][2 * np + 0], af[mt], bf[np][0], bf[np][1]);
                    MMA_16816(acc[mt][2 * np + 1], af[mt], bf[np][2], bf[np][3]);
                }
        }
    }

    // ---- epilogue: split 0 -> out, splits 1..3 -> g_P slabs ----
    float* dst = (sp == 0) ? out : (part + (size_t)(sp - 1) * NTOK * OUTF);
    int grp = lane >> 2;
    int tig = lane & 3;
#pragma unroll
    for (int mt = 0; mt < 4; mt++) {
        int mrow = m0 + wm * 64 + mt * 16 + grp;
#pragma unroll
        for (int nt = 0; nt < 4; nt++) {
            int ncol = n0 + wn * 32 + nt * 8 + tig * 2;
            float2 v0 = make_float2(acc[mt][nt][0], acc[mt][nt][1]);
            float2 v1 = make_float2(acc[mt][nt][2], acc[mt][nt][3]);
            *(float2*)(dst + (size_t)mrow * OUTF + ncol)       = v0;
            *(float2*)(dst + (size_t)(mrow + 8) * OUTF + ncol) = v1;
        }
    }
}

// ============================================================================
// Reduce: out += P1 + P2 + P3   (bias already in K tail; deterministic)
// ============================================================================
__global__ __launch_bounds__(256) void reduce_kernel(float* __restrict__ out) {
    size_t i4 = ((size_t)blockIdx.x * 256 + threadIdx.x) * 4;
    float4 a = *(float4*)(out + i4);
#pragma unroll
    for (int s = 0; s < 3; s++) {
        float4 p = *(const float4*)(g_P + (size_t)s * NTOK * OUTF + i4);
        a.x += p.x; a.y += p.y; a.z += p.z; a.w += p.w;
    }
    *(float4*)(out + i4) = a;
}

// ============================================================================
// Launch
// ============================================================================
extern "C" void kernel_launch(void* const* d_in, const int* in_sizes, int n_in,
                              void* d_out, int out_size) {
    (void)in_sizes; (void)n_in; (void)out_size;
    const float* x  = (const float*)d_in[0];   // [8192, 1024]
    const float* We = (const float*)d_in[1];   // [8, 1024, 1024]
    const float* be = (const float*)d_in[2];   // [8, 1024]
    const float* Wg = (const float*)d_in[3];   // [1024, 8]
    const float* bg = (const float*)d_in[4];   // [8]
    float* out = (float*)d_out;                // [8192, 1024]

    float* part;
    cudaGetSymbolAddress((void**)&part, g_P);

    cudaFuncSetAttribute(moe_gemm_kernel,
                         cudaFuncAttributeMaxDynamicSharedMemorySize, SMEM_BYTES);

    gate_splitx_kernel<<<NTOK / 8, 256>>>(x, Wg, bg);
    splitw_kernel<<<NE * 32 * 32, 256>>>(We);
    tail_w_kernel<<<(OUTF * 64) / 256, 256>>>(be);
    moe_gemm_kernel<<<dim3(OUTF / BN, NTOK / BM, NSPLIT), THREADS, SMEM_BYTES>>>(
        out, part);
    reduce_kernel<<<(NTOK * OUTF) / (256 * 4), 256>>>(out);
}